// round 16
// baseline (speedup 1.0000x reference)
#include <cuda_runtime.h>
#include <cuda_bf16.h>
#include <cuda_fp16.h>
#include <math.h>

// Problem constants (fixed by the dataset)
#define NN 25000
#define EE 400000
#define HH 4
#define CC 128
#define DD 128
#define HC 512           // H*C
#define WC 1664          // packed W columns: q(512) k(512) v(512) s(128)
#define SCALE 0.08838834764831845f   // 1/sqrt(128)

// ------------------------- device scratch (no runtime allocs) ---------------
static __device__ int   g_row[NN + 1];
static __device__ int   g_cnt[NN + 1];
static __device__ int   g_cursor[NN + 1];
static __device__ int   g_srcs[EE];
static __device__ __nv_bfloat16 g_qb[NN * HC];
static __device__ unsigned char g_kf[NN * HC];   // e4m3, 1B/channel
static __device__ unsigned char g_vf[NN * HC];   // e4m3
static __device__ float g_s[NN * DD];
static __device__ __nv_bfloat16 g_hA[NN * DD];
static __device__ __nv_bfloat16 g_hB[NN * DD];
static __device__ __nv_bfloat16 g_xb[NN * 64];
static __device__ __nv_bfloat16 g_wb[64 * WC + 2 * 128 * WC];  // 3 layers packed
static __device__ float g_g[DD];

// ------------------------- small kernels --------------------------------------
__global__ void zero_cnt_kernel(int* __restrict__ cnt) {
    int i = blockIdx.x * blockDim.x + threadIdx.x;
    if (i < NN + 1) cnt[i] = 0;
}

__global__ void convX_kernel(const float* __restrict__ x, __nv_bfloat16* __restrict__ xb,
                             float* __restrict__ g) {
    int i = blockIdx.x * blockDim.x + threadIdx.x;
    if (i < DD) g[i] = 0.f;
    if (i < NN * 64) xb[i] = __float2bfloat16(x[i]);
}

// all 3 layers' W -> packed bf16 [fin, 1664] in one launch
__global__ void convW_all_kernel(
    const float* __restrict__ Wq0, const float* __restrict__ Wk0,
    const float* __restrict__ Wv0, const float* __restrict__ Ws0,
    const float* __restrict__ Wq1, const float* __restrict__ Wk1,
    const float* __restrict__ Wv1, const float* __restrict__ Ws1,
    const float* __restrict__ Wq2, const float* __restrict__ Wk2,
    const float* __restrict__ Wv2, const float* __restrict__ Ws2,
    __nv_bfloat16* __restrict__ out)
{
    int i = blockIdx.x * blockDim.x + threadIdx.x;
    const int L0 = 64 * WC, L1 = 128 * WC;
    if (i >= L0 + 2 * L1) return;
    const float *Wq, *Wk, *Wv, *Ws;
    int j;
    if (i < L0)            { j = i;            Wq = Wq0; Wk = Wk0; Wv = Wv0; Ws = Ws0; }
    else if (i < L0 + L1)  { j = i - L0;       Wq = Wq1; Wk = Wk1; Wv = Wv1; Ws = Ws1; }
    else                   { j = i - L0 - L1;  Wq = Wq2; Wk = Wk2; Wv = Wv2; Ws = Ws2; }
    int r = j / WC, c = j % WC;
    float v;
    if (c < 512)       v = Wq[r * 512 + c];
    else if (c < 1024) v = Wk[r * 512 + c - 512];
    else if (c < 1536) v = Wv[r * 512 + c - 1024];
    else               v = Ws[r * 128 + c - 1536];
    out[i] = __float2bfloat16(v);
}

// ------------------------- CSR build ----------------------------------------
__global__ void hist_kernel(const int* __restrict__ dst, int* __restrict__ cnt) {
    int e = blockIdx.x * blockDim.x + threadIdx.x;
    if (e < EE) atomicAdd(&cnt[dst[e]], 1);
}

// single-block warp-shuffle scan
__global__ void scan_kernel(const int* __restrict__ cnt,
                            int* __restrict__ row, int* __restrict__ cursor) {
    __shared__ int wsum[32];
    __shared__ int woff[32];
    __shared__ int s_carry;
    int tid = threadIdx.x;
    int lane = tid & 31;
    int w = tid >> 5;
    if (tid == 0) s_carry = 0;
    __syncthreads();
    for (int base = 0; base < NN; base += 1024) {
        int i = base + tid;
        int v = (i < NN) ? cnt[i] : 0;
        int incl = v;
        #pragma unroll
        for (int off = 1; off < 32; off <<= 1) {
            int t = __shfl_up_sync(0xffffffffu, incl, off);
            if (lane >= off) incl += t;
        }
        if (lane == 31) wsum[w] = incl;
        __syncthreads();
        if (w == 0) {
            int sv = wsum[lane];
            int ws = sv;
            #pragma unroll
            for (int off = 1; off < 32; off <<= 1) {
                int t = __shfl_up_sync(0xffffffffu, ws, off);
                if (lane >= off) ws += t;
            }
            woff[lane] = ws - sv;
        }
        __syncthreads();
        int excl = incl - v + woff[w] + s_carry;
        if (i < NN) { row[i] = excl; cursor[i] = excl; }
        __syncthreads();
        if (tid == 1023) s_carry += woff[31] + wsum[31];
        __syncthreads();
    }
    if (tid == 0) row[NN] = s_carry;
}

__global__ void fill_kernel(const int* __restrict__ src, const int* __restrict__ dst,
                            int* __restrict__ cursor, int* __restrict__ srcs) {
    int e = blockIdx.x * blockDim.x + threadIdx.x;
    if (e < EE) {
        int p = atomicAdd(&cursor[dst[e]], 1);
        srcs[p] = src[e];
    }
}

// ------------------------- helpers ------------------------------------------
__device__ __forceinline__ unsigned pack_bf2(float lo, float hi) {
    unsigned r;
    asm("cvt.rn.bf16x2.f32 %0, %1, %2;" : "=r"(r) : "f"(hi), "f"(lo));
    return r;
}
__device__ __forceinline__ unsigned short pack_fp8_2(float lo, float hi) {
    unsigned short r;
    asm("cvt.rn.satfinite.e4m3x2.f32 %0, %1, %2;" : "=h"(r) : "f"(hi), "f"(lo));
    return r;
}
// 4 x e4m3 (packed in u32) -> float4
__device__ __forceinline__ float4 fp8x4_to_f4(unsigned u) {
    unsigned short lo = (unsigned short)(u & 0xffffu);
    unsigned short hi = (unsigned short)(u >> 16);
    unsigned h01, h23;
    asm("cvt.rn.f16x2.e4m3x2 %0, %1;" : "=r"(h01) : "h"(lo));
    asm("cvt.rn.f16x2.e4m3x2 %0, %1;" : "=r"(h23) : "h"(hi));
    __half2 a = *reinterpret_cast<__half2*>(&h01);
    __half2 b = *reinterpret_cast<__half2*>(&h23);
    float2 f0 = __half22float2(a);
    float2 f1 = __half22float2(b);
    return make_float4(f0.x, f0.y, f1.x, f1.y);
}
__device__ __forceinline__ float4 bf4_to_f4(uint2 raw) {
    __nv_bfloat162 p0 = *reinterpret_cast<__nv_bfloat162*>(&raw.x);
    __nv_bfloat162 p1 = *reinterpret_cast<__nv_bfloat162*>(&raw.y);
    float2 f0 = __bfloat1622float2(p0);
    float2 f1 = __bfloat1622float2(p1);
    return make_float4(f0.x, f0.y, f1.x, f1.y);
}
__device__ __forceinline__ void ldsm_x4(unsigned* r, const void* p) {
    unsigned addr = (unsigned)__cvta_generic_to_shared(p);
    asm volatile("ldmatrix.sync.aligned.m8n8.x4.shared.b16 {%0,%1,%2,%3}, [%4];"
                 : "=r"(r[0]), "=r"(r[1]), "=r"(r[2]), "=r"(r[3]) : "r"(addr));
}
__device__ __forceinline__ void ldsm_x2t(unsigned* r, const void* p) {
    unsigned addr = (unsigned)__cvta_generic_to_shared(p);
    asm volatile("ldmatrix.sync.aligned.m8n8.x2.trans.shared.b16 {%0,%1}, [%2];"
                 : "=r"(r[0]), "=r"(r[1]) : "r"(addr));
}
__device__ __forceinline__ void mma_bf16(float* d, const unsigned* a, const unsigned* b) {
    asm volatile(
        "mma.sync.aligned.m16n8k16.row.col.f32.bf16.bf16.f32 "
        "{%0,%1,%2,%3}, {%4,%5,%6,%7}, {%8,%9}, {%0,%1,%2,%3};"
        : "+f"(d[0]), "+f"(d[1]), "+f"(d[2]), "+f"(d[3])
        : "r"(a[0]), "r"(a[1]), "r"(a[2]), "r"(a[3]),
          "r"(b[0]), "r"(b[1]));
}
__device__ __forceinline__ void cp_async16(unsigned smem_addr, const void* gptr) {
    asm volatile("cp.async.cg.shared.global [%0], [%1], 16;"
                 :: "r"(smem_addr), "l"(gptr));
}

// ------------------------- fused 4-way GEMM (bf16, cp.async 3-stage) ---------
#define A_BYTES (128 * 40 * 2)
#define B_BYTES (32 * 136 * 2)
#define STG_BYTES (A_BYTES + B_BYTES)
#define NSTAGE 3
#define GEMM_SMEM (NSTAGE * STG_BYTES)

__global__ __launch_bounds__(256, 2)
void gemm4_kernel(const __nv_bfloat16* __restrict__ X, int rows, int K,
                  const __nv_bfloat16* __restrict__ Wall,
                  const float* __restrict__ bq, const float* __restrict__ bk,
                  const float* __restrict__ bv, const float* __restrict__ bsk,
                  __nv_bfloat16* __restrict__ oqb, unsigned char* __restrict__ okf,
                  unsigned char* __restrict__ ovf, float* __restrict__ osk)
{
    extern __shared__ __align__(16) char smem[];
    __shared__ float sbias[128];
    unsigned sbase = (unsigned)__cvta_generic_to_shared(smem);

    int tid  = threadIdx.x;
    int wid  = tid >> 5;
    int lane = tid & 31;
    int warp_m = wid >> 2;
    int warp_n = wid & 3;
    int m0w = warp_m * 64;
    int n0w = warp_n * 32;

    int tile = blockIdx.x;          // 0..12
    int seg = tile >> 2;
    int c0 = (tile & 3) * 128;
    int wcol0 = (seg < 3) ? seg * 512 + c0 : 1536;

    const float* bias;
    if (seg == 0)      bias = bq;
    else if (seg == 1) bias = bk;
    else if (seg == 2) bias = bv;
    else               bias = bsk;

    int oc = (seg == 3) ? DD : HC;
    int row0 = blockIdx.y * 128;

    if (tid < 128) sbias[tid] = bias[c0 + tid];

    float acc[4][4][4];
    #pragma unroll
    for (int i = 0; i < 4; i++)
        #pragma unroll
        for (int j = 0; j < 4; j++)
            #pragma unroll
            for (int r = 0; r < 4; r++) acc[i][j][r] = 0.f;

    int rloc = lane >> 2;
    int cloc = lane & 3;
    int nIter = K >> 5;

    #define LOAD_TILES(it)                                                        \
    {                                                                             \
        int k0 = (it) * 32;                                                       \
        unsigned stg = sbase + ((it) % NSTAGE) * STG_BYTES;                       \
        _Pragma("unroll")                                                         \
        for (int t = 0; t < 2; ++t) {                                             \
            int id = tid + t * 256;                                               \
            int r = id >> 2, c16 = id & 3;                                        \
            int gr = row0 + r; if (gr > rows - 1) gr = rows - 1;                  \
            cp_async16(stg + r * 80 + c16 * 16,                                   \
                       X + (size_t)gr * K + k0 + c16 * 8);                        \
        }                                                                         \
        _Pragma("unroll")                                                         \
        for (int t = 0; t < 2; ++t) {                                             \
            int id = tid + t * 256;                                               \
            int kr = id >> 4, c16 = id & 15;                                      \
            cp_async16(stg + A_BYTES + kr * 272 + c16 * 16,                       \
                       Wall + (size_t)(k0 + kr) * WC + wcol0 + c16 * 8);          \
        }                                                                         \
        asm volatile("cp.async.commit_group;");                                   \
    }

    LOAD_TILES(0);
    if (nIter > 1) LOAD_TILES(1);

    for (int it = 0; it < nIter; ++it) {
        if (it + 1 < nIter) asm volatile("cp.async.wait_group 1;");
        else                asm volatile("cp.async.wait_group 0;");
        __syncthreads();
        if (it + 2 < nIter) LOAD_TILES(it + 2);

        const __nv_bfloat16* sA =
            reinterpret_cast<const __nv_bfloat16*>(smem + (it % NSTAGE) * STG_BYTES);
        const __nv_bfloat16* sB =
            reinterpret_cast<const __nv_bfloat16*>(smem + (it % NSTAGE) * STG_BYTES + A_BYTES);
        #pragma unroll
        for (int ks = 0; ks < 32; ks += 16) {
            unsigned afr[4][4];
            #pragma unroll
            for (int mt = 0; mt < 4; ++mt)
                ldsm_x4(afr[mt], sA + (m0w + mt * 16 + (lane & 15)) * 40 + ks + (lane >> 4) * 8);
            unsigned bfr[4][2];
            #pragma unroll
            for (int nt = 0; nt < 4; ++nt)
                ldsm_x2t(bfr[nt], sB + (ks + (lane & 15)) * 136 + n0w + nt * 8);
            #pragma unroll
            for (int mt = 0; mt < 4; ++mt)
                #pragma unroll
                for (int nt = 0; nt < 4; ++nt)
                    mma_bf16(acc[mt][nt], afr[mt], bfr[nt]);
        }
    }
    #undef LOAD_TILES

    #pragma unroll
    for (int mt = 0; mt < 4; ++mt) {
        int gr0 = row0 + m0w + mt * 16 + rloc;
        int gr1 = gr0 + 8;
        #pragma unroll
        for (int nt = 0; nt < 4; ++nt) {
            int colL = n0w + nt * 8 + cloc * 2;
            int gcol = c0 + colL;
            float b0 = sbias[colL];
            float b1 = sbias[colL + 1];
            float v00 = acc[mt][nt][0] + b0, v01 = acc[mt][nt][1] + b1;
            float v10 = acc[mt][nt][2] + b0, v11 = acc[mt][nt][3] + b1;
            if (seg == 3) {
                if (gr0 < rows)
                    *reinterpret_cast<float2*>(osk + (size_t)gr0 * oc + gcol) = make_float2(v00, v01);
                if (gr1 < rows)
                    *reinterpret_cast<float2*>(osk + (size_t)gr1 * oc + gcol) = make_float2(v10, v11);
            } else if (seg == 0) {
                if (gr0 < rows)
                    *reinterpret_cast<unsigned*>(oqb + (size_t)gr0 * oc + gcol) = pack_bf2(v00, v01);
                if (gr1 < rows)
                    *reinterpret_cast<unsigned*>(oqb + (size_t)gr1 * oc + gcol) = pack_bf2(v10, v11);
            } else {
                unsigned char* Y = (seg == 1) ? okf : ovf;
                if (gr0 < rows)
                    *reinterpret_cast<unsigned short*>(Y + (size_t)gr0 * oc + gcol) = pack_fp8_2(v00, v01);
                if (gr1 < rows)
                    *reinterpret_cast<unsigned short*>(Y + (size_t)gr1 * oc + gcol) = pack_fp8_2(v10, v11);
            }
        }
    }
}

// ------------------------- fused attention per node --------------------------
// 4 warps (head each), one block per node. k/v fp8 e4m3, q bf16.
// ALL edges in masked groups of 8 (clamped index, p=0 beyond end) — no serial
// tail. No-max softmax (alpha ~ N(0,1), clamp 60).
__global__ void attn_kernel(const __nv_bfloat16* __restrict__ qb,
                            const unsigned char* __restrict__ kf,
                            const unsigned char* __restrict__ vf,
                            const float* __restrict__ s,
                            const int* __restrict__ row, const int* __restrict__ srcs,
                            __nv_bfloat16* __restrict__ out) {
    int n = blockIdx.x;
    int tid = threadIdx.x;
    int h = tid >> 5;
    int lane = tid & 31;
    __shared__ float sh[HH][CC];

    uint2 qraw = reinterpret_cast<const uint2*>(qb + (size_t)n * HC + h * CC)[lane];
    const float4 qv = bf4_to_f4(qraw);
    int beg = row[n], end = row[n + 1];
    size_t hoff = (size_t)h * CC;   // bytes (1B/channel)

    float l = 0.f;
    float4 acc = make_float4(0.f, 0.f, 0.f, 0.f);

    int deg = end - beg;
    int ng = (deg + 7) >> 3;        // masked groups of 8 (covers all edges)

    unsigned kc[8], vc[8], kn[8], vn[8];

    if (ng > 0) {
        #pragma unroll
        for (int e = 0; e < 8; ++e) {
            int j = beg + e; if (j > end - 1) j = end - 1;
            int si = __ldg(&srcs[j]);
            kc[e] = reinterpret_cast<const unsigned*>(kf + (size_t)si * HC + hoff)[lane];
            vc[e] = reinterpret_cast<const unsigned*>(vf + (size_t)si * HC + hoff)[lane];
        }
    }

    for (int g = 0; g < ng; ++g) {
        if (g + 1 < ng) {
            int b2 = beg + (g + 1) * 8;
            #pragma unroll
            for (int e = 0; e < 8; ++e) {
                int j = b2 + e; if (j > end - 1) j = end - 1;
                int si = __ldg(&srcs[j]);
                kn[e] = reinterpret_cast<const unsigned*>(kf + (size_t)si * HC + hoff)[lane];
                vn[e] = reinterpret_cast<const unsigned*>(vf + (size_t)si * HC + hoff)[lane];
            }
        }
        float d[8];
        #pragma unroll
        for (int e = 0; e < 8; ++e) {
            float4 kv = fp8x4_to_f4(kc[e]);
            d[e] = qv.x * kv.x + qv.y * kv.y + qv.z * kv.z + qv.w * kv.w;
        }
        #pragma unroll
        for (int off = 16; off > 0; off >>= 1) {
            #pragma unroll
            for (int e = 0; e < 8; ++e)
                d[e] += __shfl_xor_sync(0xffffffffu, d[e], off);
        }
        int rem = end - (beg + g * 8);       // edges remaining in this group
        float p[8];
        #pragma unroll
        for (int e = 0; e < 8; ++e) {
            p[e] = __expf(fminf(d[e] * SCALE, 60.f));
            if (e >= rem) p[e] = 0.f;        // mask out-of-range edges
        }
        #pragma unroll
        for (int e = 0; e < 8; ++e) {
            float4 fv = fp8x4_to_f4(vc[e]);
            acc.x += p[e] * fv.x;
            acc.y += p[e] * fv.y;
            acc.z += p[e] * fv.z;
            acc.w += p[e] * fv.w;
            l += p[e];
        }
        #pragma unroll
        for (int e = 0; e < 8; ++e) { kc[e] = kn[e]; vc[e] = vn[e]; }
    }

    float invl = 1.f / (l + 1e-16f);
    sh[h][lane * 4 + 0] = acc.x * invl;
    sh[h][lane * 4 + 1] = acc.y * invl;
    sh[h][lane * 4 + 2] = acc.z * invl;
    sh[h][lane * 4 + 3] = acc.w * invl;
    __syncthreads();

    float val = (sh[0][tid] + sh[1][tid] + sh[2][tid] + sh[3][tid]) * 0.25f
              + s[(size_t)n * DD + tid];
    out[(size_t)n * DD + tid] = __float2bfloat16(fmaxf(val, 0.f));
}

// ------------------------- tail: mean over nodes, fc, sigmoid ---------------
__global__ void reduce_cols_kernel(const __nv_bfloat16* __restrict__ hbuf, float* __restrict__ g) {
    int c = threadIdx.x;
    float a = 0.f;
    for (int r = blockIdx.x; r < NN; r += gridDim.x)
        a += __bfloat162float(hbuf[(size_t)r * DD + c]);
    atomicAdd(&g[c], a);
}

__global__ void fc_kernel(const float* __restrict__ g, const float* __restrict__ Wfc,
                          const float* __restrict__ bfc, float* __restrict__ out) {
    int tid = threadIdx.x;
    float x = g[tid] * (1.0f / (float)NN) * Wfc[tid];
    #pragma unroll
    for (int off = 16; off > 0; off >>= 1)
        x += __shfl_xor_sync(0xffffffffu, x, off);
    __shared__ float ws[4];
    if ((tid & 31) == 0) ws[tid >> 5] = x;
    __syncthreads();
    if (tid == 0) {
        float sum = ws[0] + ws[1] + ws[2] + ws[3] + bfc[0];
        out[0] = 1.f / (1.f + expf(-sum));
    }
}

// ------------------------- launch -------------------------------------------
extern "C" void kernel_launch(void* const* d_in, const int* in_sizes, int n_in,
                              void* d_out, int out_size) {
    (void)in_sizes; (void)n_in; (void)out_size;

    const float* x    = (const float*)d_in[0];
    const int*   eidx = (const int*)d_in[1];
    const int*   src  = eidx;
    const int*   dst  = eidx + EE;
    const float* Wfc  = (const float*)d_in[26];
    const float* bfc  = (const float*)d_in[27];
    float* out = (float*)d_out;

    int *row, *cnt, *cursor, *srcs;
    float *s, *g;
    __nv_bfloat16 *qbp, *hA, *hB, *xb, *wb;
    unsigned char *kfp, *vfp;
    cudaGetSymbolAddress((void**)&row,    g_row);
    cudaGetSymbolAddress((void**)&cnt,    g_cnt);
    cudaGetSymbolAddress((void**)&cursor, g_cursor);
    cudaGetSymbolAddress((void**)&srcs,   g_srcs);
    cudaGetSymbolAddress((void**)&qbp,    g_qb);
    cudaGetSymbolAddress((void**)&kfp,    g_kf);
    cudaGetSymbolAddress((void**)&vfp,    g_vf);
    cudaGetSymbolAddress((void**)&s,      g_s);
    cudaGetSymbolAddress((void**)&hA,     g_hA);
    cudaGetSymbolAddress((void**)&hB,     g_hB);
    cudaGetSymbolAddress((void**)&xb,     g_xb);
    cudaGetSymbolAddress((void**)&wb,     g_wb);
    cudaGetSymbolAddress((void**)&g,      g_g);

    cudaFuncSetAttribute(gemm4_kernel,
                         cudaFuncAttributeMaxDynamicSharedMemorySize, GEMM_SMEM);

    // lazy one-time streams/events (no device memory; capture-legal fork/join)
    static cudaStream_t s2 = nullptr, s3 = nullptr;
    static cudaEvent_t evFork = nullptr, evCSR = nullptr, evW = nullptr;
    if (s2 == nullptr) {
        cudaStreamCreateWithFlags(&s2, cudaStreamNonBlocking);
        cudaStreamCreateWithFlags(&s3, cudaStreamNonBlocking);
        cudaEventCreateWithFlags(&evFork, cudaEventDisableTiming);
        cudaEventCreateWithFlags(&evCSR,  cudaEventDisableTiming);
        cudaEventCreateWithFlags(&evW,    cudaEventDisableTiming);
    }

    size_t wboff[3] = {0, (size_t)64 * WC, (size_t)64 * WC + (size_t)128 * WC};

    // ---- fork ----
    cudaEventRecord(evFork, 0);
    cudaStreamWaitEvent(s2, evFork, 0);
    cudaStreamWaitEvent(s3, evFork, 0);

    // s2: convW (needed by gemm0)
    {
        int total = 64 * WC + 2 * 128 * WC;
        convW_all_kernel<<<(total + 255) / 256, 256, 0, s2>>>(
            (const float*)d_in[2],  (const float*)d_in[4],
            (const float*)d_in[6],  (const float*)d_in[8],
            (const float*)d_in[10], (const float*)d_in[12],
            (const float*)d_in[14], (const float*)d_in[16],
            (const float*)d_in[18], (const float*)d_in[20],
            (const float*)d_in[22], (const float*)d_in[24],
            wb);
    }
    cudaEventRecord(evW, s2);

    // s3: CSR build (needed by attn0)
    zero_cnt_kernel<<<(NN + 256) / 256, 256, 0, s3>>>(cnt);
    hist_kernel<<<(EE + 255) / 256, 256, 0, s3>>>(dst, cnt);
    scan_kernel<<<1, 1024, 0, s3>>>(cnt, row, cursor);
    fill_kernel<<<(EE + 255) / 256, 256, 0, s3>>>(src, dst, cursor, srcs);
    cudaEventRecord(evCSR, s3);

    // main: convX concurrent with convW/CSR
    convX_kernel<<<(NN * 64 + 255) / 256, 256>>>(x, xb, g);
    cudaStreamWaitEvent(0, evW, 0);     // gemm0 needs wb

    const __nv_bfloat16* X = xb;
    int fin = 64;
    __nv_bfloat16* hout = hA;
    for (int l = 0; l < 3; ++l) {
        const float* bq = (const float*)d_in[2 + 8 * l + 1];
        const float* bk = (const float*)d_in[2 + 8 * l + 3];
        const float* bv = (const float*)d_in[2 + 8 * l + 5];
        const float* bs = (const float*)d_in[2 + 8 * l + 7];

        dim3 grid(13, (NN + 127) / 128);
        gemm4_kernel<<<grid, 256, GEMM_SMEM>>>(X, NN, fin, wb + wboff[l],
                                               bq, bk, bv, bs,
                                               qbp, kfp, vfp, s);

        if (l == 0)   // join: CSR results needed from here on
            cudaStreamWaitEvent(0, evCSR, 0);

        attn_kernel<<<NN, 128>>>(qbp, kfp, vfp, s, row, srcs, hout);

        X = hout;
        hout = (hout == hA) ? hB : hA;
        fin = DD;
    }

    // ---- global mean + fc + sigmoid ----
    reduce_cols_kernel<<<256, 128>>>(X, g);
    fc_kernel<<<1, 128>>>(g, Wfc, bfc, out);
}

// round 17
// speedup vs baseline: 1.2188x; 1.2188x over previous
#include <cuda_runtime.h>
#include <cuda_bf16.h>
#include <cuda_fp16.h>
#include <math.h>

// Problem constants (fixed by the dataset)
#define NN 25000
#define EE 400000
#define HH 4
#define CC 128
#define DD 128
#define HC 512           // H*C
#define WC 1664          // packed W columns: q(512) k(512) v(512) s(128)
#define SCALE 0.08838834764831845f   // 1/sqrt(128)

// ------------------------- device scratch (no runtime allocs) ---------------
static __device__ int   g_row[NN + 1];
static __device__ int   g_cnt[NN + 1];
static __device__ int   g_cursor[NN + 1];
static __device__ int   g_srcs[EE];
static __device__ __nv_bfloat16 g_qb[NN * HC];
static __device__ unsigned char g_kf[NN * HC];   // e4m3, 1B/channel
static __device__ unsigned char g_vf[NN * HC];   // e4m3
static __device__ float g_s[NN * DD];
static __device__ __nv_bfloat16 g_hA[NN * DD];
static __device__ __nv_bfloat16 g_hB[NN * DD];
static __device__ __nv_bfloat16 g_xb[NN * 64];
static __device__ __nv_bfloat16 g_wb[64 * WC + 2 * 128 * WC];  // 3 layers packed
static __device__ float g_g[DD];

// ------------------------- small kernels --------------------------------------
__global__ void zero_cnt_kernel(int* __restrict__ cnt) {
    int i = blockIdx.x * blockDim.x + threadIdx.x;
    if (i < NN + 1) cnt[i] = 0;
}

__global__ void convX_kernel(const float* __restrict__ x, __nv_bfloat16* __restrict__ xb,
                             float* __restrict__ g) {
    int i = blockIdx.x * blockDim.x + threadIdx.x;
    if (i < DD) g[i] = 0.f;
    if (i < NN * 64) xb[i] = __float2bfloat16(x[i]);
}

// all 3 layers' W -> packed bf16 [fin, 1664] in one launch
__global__ void convW_all_kernel(
    const float* __restrict__ Wq0, const float* __restrict__ Wk0,
    const float* __restrict__ Wv0, const float* __restrict__ Ws0,
    const float* __restrict__ Wq1, const float* __restrict__ Wk1,
    const float* __restrict__ Wv1, const float* __restrict__ Ws1,
    const float* __restrict__ Wq2, const float* __restrict__ Wk2,
    const float* __restrict__ Wv2, const float* __restrict__ Ws2,
    __nv_bfloat16* __restrict__ out)
{
    int i = blockIdx.x * blockDim.x + threadIdx.x;
    const int L0 = 64 * WC, L1 = 128 * WC;
    if (i >= L0 + 2 * L1) return;
    const float *Wq, *Wk, *Wv, *Ws;
    int j;
    if (i < L0)            { j = i;            Wq = Wq0; Wk = Wk0; Wv = Wv0; Ws = Ws0; }
    else if (i < L0 + L1)  { j = i - L0;       Wq = Wq1; Wk = Wk1; Wv = Wv1; Ws = Ws1; }
    else                   { j = i - L0 - L1;  Wq = Wq2; Wk = Wk2; Wv = Wv2; Ws = Ws2; }
    int r = j / WC, c = j % WC;
    float v;
    if (c < 512)       v = Wq[r * 512 + c];
    else if (c < 1024) v = Wk[r * 512 + c - 512];
    else if (c < 1536) v = Wv[r * 512 + c - 1024];
    else               v = Ws[r * 128 + c - 1536];
    out[i] = __float2bfloat16(v);
}

// ------------------------- CSR build ----------------------------------------
__global__ void hist_kernel(const int* __restrict__ dst, int* __restrict__ cnt) {
    int e = blockIdx.x * blockDim.x + threadIdx.x;
    if (e < EE) atomicAdd(&cnt[dst[e]], 1);
}

// single-block warp-shuffle scan
__global__ void scan_kernel(const int* __restrict__ cnt,
                            int* __restrict__ row, int* __restrict__ cursor) {
    __shared__ int wsum[32];
    __shared__ int woff[32];
    __shared__ int s_carry;
    int tid = threadIdx.x;
    int lane = tid & 31;
    int w = tid >> 5;
    if (tid == 0) s_carry = 0;
    __syncthreads();
    for (int base = 0; base < NN; base += 1024) {
        int i = base + tid;
        int v = (i < NN) ? cnt[i] : 0;
        int incl = v;
        #pragma unroll
        for (int off = 1; off < 32; off <<= 1) {
            int t = __shfl_up_sync(0xffffffffu, incl, off);
            if (lane >= off) incl += t;
        }
        if (lane == 31) wsum[w] = incl;
        __syncthreads();
        if (w == 0) {
            int sv = wsum[lane];
            int ws = sv;
            #pragma unroll
            for (int off = 1; off < 32; off <<= 1) {
                int t = __shfl_up_sync(0xffffffffu, ws, off);
                if (lane >= off) ws += t;
            }
            woff[lane] = ws - sv;
        }
        __syncthreads();
        int excl = incl - v + woff[w] + s_carry;
        if (i < NN) { row[i] = excl; cursor[i] = excl; }
        __syncthreads();
        if (tid == 1023) s_carry += woff[31] + wsum[31];
        __syncthreads();
    }
    if (tid == 0) row[NN] = s_carry;
}

__global__ void fill_kernel(const int* __restrict__ src, const int* __restrict__ dst,
                            int* __restrict__ cursor, int* __restrict__ srcs) {
    int e = blockIdx.x * blockDim.x + threadIdx.x;
    if (e < EE) {
        int p = atomicAdd(&cursor[dst[e]], 1);
        srcs[p] = src[e];
    }
}

// ------------------------- helpers ------------------------------------------
__device__ __forceinline__ unsigned pack_bf2(float lo, float hi) {
    unsigned r;
    asm("cvt.rn.bf16x2.f32 %0, %1, %2;" : "=r"(r) : "f"(hi), "f"(lo));
    return r;
}
__device__ __forceinline__ unsigned short pack_fp8_2(float lo, float hi) {
    unsigned short r;
    asm("cvt.rn.satfinite.e4m3x2.f32 %0, %1, %2;" : "=h"(r) : "f"(hi), "f"(lo));
    return r;
}
// 4 x e4m3 (packed in u32) -> float4
__device__ __forceinline__ float4 fp8x4_to_f4(unsigned u) {
    unsigned short lo = (unsigned short)(u & 0xffffu);
    unsigned short hi = (unsigned short)(u >> 16);
    unsigned h01, h23;
    asm("cvt.rn.f16x2.e4m3x2 %0, %1;" : "=r"(h01) : "h"(lo));
    asm("cvt.rn.f16x2.e4m3x2 %0, %1;" : "=r"(h23) : "h"(hi));
    __half2 a = *reinterpret_cast<__half2*>(&h01);
    __half2 b = *reinterpret_cast<__half2*>(&h23);
    float2 f0 = __half22float2(a);
    float2 f1 = __half22float2(b);
    return make_float4(f0.x, f0.y, f1.x, f1.y);
}
__device__ __forceinline__ float4 bf4_to_f4(uint2 raw) {
    __nv_bfloat162 p0 = *reinterpret_cast<__nv_bfloat162*>(&raw.x);
    __nv_bfloat162 p1 = *reinterpret_cast<__nv_bfloat162*>(&raw.y);
    float2 f0 = __bfloat1622float2(p0);
    float2 f1 = __bfloat1622float2(p1);
    return make_float4(f0.x, f0.y, f1.x, f1.y);
}
__device__ __forceinline__ void ldsm_x4(unsigned* r, const void* p) {
    unsigned addr = (unsigned)__cvta_generic_to_shared(p);
    asm volatile("ldmatrix.sync.aligned.m8n8.x4.shared.b16 {%0,%1,%2,%3}, [%4];"
                 : "=r"(r[0]), "=r"(r[1]), "=r"(r[2]), "=r"(r[3]) : "r"(addr));
}
__device__ __forceinline__ void ldsm_x2t(unsigned* r, const void* p) {
    unsigned addr = (unsigned)__cvta_generic_to_shared(p);
    asm volatile("ldmatrix.sync.aligned.m8n8.x2.trans.shared.b16 {%0,%1}, [%2];"
                 : "=r"(r[0]), "=r"(r[1]) : "r"(addr));
}
__device__ __forceinline__ void mma_bf16(float* d, const unsigned* a, const unsigned* b) {
    asm volatile(
        "mma.sync.aligned.m16n8k16.row.col.f32.bf16.bf16.f32 "
        "{%0,%1,%2,%3}, {%4,%5,%6,%7}, {%8,%9}, {%0,%1,%2,%3};"
        : "+f"(d[0]), "+f"(d[1]), "+f"(d[2]), "+f"(d[3])
        : "r"(a[0]), "r"(a[1]), "r"(a[2]), "r"(a[3]),
          "r"(b[0]), "r"(b[1]));
}
__device__ __forceinline__ void cp_async16(unsigned smem_addr, const void* gptr) {
    asm volatile("cp.async.cg.shared.global [%0], [%1], 16;"
                 :: "r"(smem_addr), "l"(gptr));
}

// ------------------------- fused 4-way GEMM (bf16, cp.async 3-stage) ---------
#define A_BYTES (128 * 40 * 2)
#define B_BYTES (32 * 136 * 2)
#define STG_BYTES (A_BYTES + B_BYTES)
#define NSTAGE 3
#define GEMM_SMEM (NSTAGE * STG_BYTES)

__global__ __launch_bounds__(256, 2)
void gemm4_kernel(const __nv_bfloat16* __restrict__ X, int rows, int K,
                  const __nv_bfloat16* __restrict__ Wall,
                  const float* __restrict__ bq, const float* __restrict__ bk,
                  const float* __restrict__ bv, const float* __restrict__ bsk,
                  __nv_bfloat16* __restrict__ oqb, unsigned char* __restrict__ okf,
                  unsigned char* __restrict__ ovf, float* __restrict__ osk)
{
    extern __shared__ __align__(16) char smem[];
    __shared__ float sbias[128];
    unsigned sbase = (unsigned)__cvta_generic_to_shared(smem);

    int tid  = threadIdx.x;
    int wid  = tid >> 5;
    int lane = tid & 31;
    int warp_m = wid >> 2;
    int warp_n = wid & 3;
    int m0w = warp_m * 64;
    int n0w = warp_n * 32;

    int tile = blockIdx.x;          // 0..12
    int seg = tile >> 2;
    int c0 = (tile & 3) * 128;
    int wcol0 = (seg < 3) ? seg * 512 + c0 : 1536;

    const float* bias;
    if (seg == 0)      bias = bq;
    else if (seg == 1) bias = bk;
    else if (seg == 2) bias = bv;
    else               bias = bsk;

    int oc = (seg == 3) ? DD : HC;
    int row0 = blockIdx.y * 128;

    if (tid < 128) sbias[tid] = bias[c0 + tid];

    float acc[4][4][4];
    #pragma unroll
    for (int i = 0; i < 4; i++)
        #pragma unroll
        for (int j = 0; j < 4; j++)
            #pragma unroll
            for (int r = 0; r < 4; r++) acc[i][j][r] = 0.f;

    int rloc = lane >> 2;
    int cloc = lane & 3;
    int nIter = K >> 5;

    #define LOAD_TILES(it)                                                        \
    {                                                                             \
        int k0 = (it) * 32;                                                       \
        unsigned stg = sbase + ((it) % NSTAGE) * STG_BYTES;                       \
        _Pragma("unroll")                                                         \
        for (int t = 0; t < 2; ++t) {                                             \
            int id = tid + t * 256;                                               \
            int r = id >> 2, c16 = id & 3;                                        \
            int gr = row0 + r; if (gr > rows - 1) gr = rows - 1;                  \
            cp_async16(stg + r * 80 + c16 * 16,                                   \
                       X + (size_t)gr * K + k0 + c16 * 8);                        \
        }                                                                         \
        _Pragma("unroll")                                                         \
        for (int t = 0; t < 2; ++t) {                                             \
            int id = tid + t * 256;                                               \
            int kr = id >> 4, c16 = id & 15;                                      \
            cp_async16(stg + A_BYTES + kr * 272 + c16 * 16,                       \
                       Wall + (size_t)(k0 + kr) * WC + wcol0 + c16 * 8);          \
        }                                                                         \
        asm volatile("cp.async.commit_group;");                                   \
    }

    LOAD_TILES(0);
    if (nIter > 1) LOAD_TILES(1);

    for (int it = 0; it < nIter; ++it) {
        if (it + 1 < nIter) asm volatile("cp.async.wait_group 1;");
        else                asm volatile("cp.async.wait_group 0;");
        __syncthreads();
        if (it + 2 < nIter) LOAD_TILES(it + 2);

        const __nv_bfloat16* sA =
            reinterpret_cast<const __nv_bfloat16*>(smem + (it % NSTAGE) * STG_BYTES);
        const __nv_bfloat16* sB =
            reinterpret_cast<const __nv_bfloat16*>(smem + (it % NSTAGE) * STG_BYTES + A_BYTES);
        #pragma unroll
        for (int ks = 0; ks < 32; ks += 16) {
            unsigned afr[4][4];
            #pragma unroll
            for (int mt = 0; mt < 4; ++mt)
                ldsm_x4(afr[mt], sA + (m0w + mt * 16 + (lane & 15)) * 40 + ks + (lane >> 4) * 8);
            unsigned bfr[4][2];
            #pragma unroll
            for (int nt = 0; nt < 4; ++nt)
                ldsm_x2t(bfr[nt], sB + (ks + (lane & 15)) * 136 + n0w + nt * 8);
            #pragma unroll
            for (int mt = 0; mt < 4; ++mt)
                #pragma unroll
                for (int nt = 0; nt < 4; ++nt)
                    mma_bf16(acc[mt][nt], afr[mt], bfr[nt]);
        }
    }
    #undef LOAD_TILES

    #pragma unroll
    for (int mt = 0; mt < 4; ++mt) {
        int gr0 = row0 + m0w + mt * 16 + rloc;
        int gr1 = gr0 + 8;
        #pragma unroll
        for (int nt = 0; nt < 4; ++nt) {
            int colL = n0w + nt * 8 + cloc * 2;
            int gcol = c0 + colL;
            float b0 = sbias[colL];
            float b1 = sbias[colL + 1];
            float v00 = acc[mt][nt][0] + b0, v01 = acc[mt][nt][1] + b1;
            float v10 = acc[mt][nt][2] + b0, v11 = acc[mt][nt][3] + b1;
            if (seg == 3) {
                if (gr0 < rows)
                    *reinterpret_cast<float2*>(osk + (size_t)gr0 * oc + gcol) = make_float2(v00, v01);
                if (gr1 < rows)
                    *reinterpret_cast<float2*>(osk + (size_t)gr1 * oc + gcol) = make_float2(v10, v11);
            } else if (seg == 0) {
                if (gr0 < rows)
                    *reinterpret_cast<unsigned*>(oqb + (size_t)gr0 * oc + gcol) = pack_bf2(v00, v01);
                if (gr1 < rows)
                    *reinterpret_cast<unsigned*>(oqb + (size_t)gr1 * oc + gcol) = pack_bf2(v10, v11);
            } else {
                unsigned char* Y = (seg == 1) ? okf : ovf;
                if (gr0 < rows)
                    *reinterpret_cast<unsigned short*>(Y + (size_t)gr0 * oc + gcol) = pack_fp8_2(v00, v01);
                if (gr1 < rows)
                    *reinterpret_cast<unsigned short*>(Y + (size_t)gr1 * oc + gcol) = pack_fp8_2(v10, v11);
            }
        }
    }
}

// ------------------------- fused attention per node --------------------------
// 4 warps (head each), one block per node. k/v fp8 e4m3, q bf16.
// Groups of 8 edges, register double-buffered + serial tail (R14 design).
__global__ void attn_kernel(const __nv_bfloat16* __restrict__ qb,
                            const unsigned char* __restrict__ kf,
                            const unsigned char* __restrict__ vf,
                            const float* __restrict__ s,
                            const int* __restrict__ row, const int* __restrict__ srcs,
                            __nv_bfloat16* __restrict__ out) {
    int n = blockIdx.x;
    int tid = threadIdx.x;
    int h = tid >> 5;
    int lane = tid & 31;
    __shared__ float sh[HH][CC];

    uint2 qraw = reinterpret_cast<const uint2*>(qb + (size_t)n * HC + h * CC)[lane];
    const float4 qv = bf4_to_f4(qraw);
    int beg = row[n], end = row[n + 1];
    size_t hoff = (size_t)h * CC;   // bytes (1B/channel)

    float l = 0.f;
    float4 acc = make_float4(0.f, 0.f, 0.f, 0.f);

    int deg = end - beg;
    int ng = deg >> 3;              // groups of 8

    unsigned kc[8], vc[8], kn[8], vn[8];

    if (ng > 0) {
        #pragma unroll
        for (int e = 0; e < 8; ++e) {
            int si = __ldg(&srcs[beg + e]);
            kc[e] = reinterpret_cast<const unsigned*>(kf + (size_t)si * HC + hoff)[lane];
            vc[e] = reinterpret_cast<const unsigned*>(vf + (size_t)si * HC + hoff)[lane];
        }
    }

    for (int g = 0; g < ng; ++g) {
        if (g + 1 < ng) {
            int b2 = beg + (g + 1) * 8;
            #pragma unroll
            for (int e = 0; e < 8; ++e) {
                int si = __ldg(&srcs[b2 + e]);
                kn[e] = reinterpret_cast<const unsigned*>(kf + (size_t)si * HC + hoff)[lane];
                vn[e] = reinterpret_cast<const unsigned*>(vf + (size_t)si * HC + hoff)[lane];
            }
        }
        float d[8];
        #pragma unroll
        for (int e = 0; e < 8; ++e) {
            float4 kv = fp8x4_to_f4(kc[e]);
            d[e] = qv.x * kv.x + qv.y * kv.y + qv.z * kv.z + qv.w * kv.w;
        }
        #pragma unroll
        for (int off = 16; off > 0; off >>= 1) {
            #pragma unroll
            for (int e = 0; e < 8; ++e)
                d[e] += __shfl_xor_sync(0xffffffffu, d[e], off);
        }
        float p[8];
        #pragma unroll
        for (int e = 0; e < 8; ++e)
            p[e] = __expf(fminf(d[e] * SCALE, 60.f));
        #pragma unroll
        for (int e = 0; e < 8; ++e) {
            float4 fv = fp8x4_to_f4(vc[e]);
            acc.x += p[e] * fv.x;
            acc.y += p[e] * fv.y;
            acc.z += p[e] * fv.z;
            acc.w += p[e] * fv.w;
            l += p[e];
        }
        #pragma unroll
        for (int e = 0; e < 8; ++e) { kc[e] = kn[e]; vc[e] = vn[e]; }
    }

    for (int j = beg + ng * 8; j < end; ++j) {
        int si = __ldg(&srcs[j]);
        unsigned kr = reinterpret_cast<const unsigned*>(kf + (size_t)si * HC + hoff)[lane];
        unsigned vr = reinterpret_cast<const unsigned*>(vf + (size_t)si * HC + hoff)[lane];
        float4 kv = fp8x4_to_f4(kr);
        float part = qv.x * kv.x + qv.y * kv.y + qv.z * kv.z + qv.w * kv.w;
        #pragma unroll
        for (int off = 16; off > 0; off >>= 1)
            part += __shfl_xor_sync(0xffffffffu, part, off);
        float pp = __expf(fminf(part * SCALE, 60.f));
        float4 vv = fp8x4_to_f4(vr);
        acc.x += pp * vv.x;
        acc.y += pp * vv.y;
        acc.z += pp * vv.z;
        acc.w += pp * vv.w;
        l += pp;
    }

    float invl = 1.f / (l + 1e-16f);
    sh[h][lane * 4 + 0] = acc.x * invl;
    sh[h][lane * 4 + 1] = acc.y * invl;
    sh[h][lane * 4 + 2] = acc.z * invl;
    sh[h][lane * 4 + 3] = acc.w * invl;
    __syncthreads();

    float val = (sh[0][tid] + sh[1][tid] + sh[2][tid] + sh[3][tid]) * 0.25f
              + s[(size_t)n * DD + tid];
    out[(size_t)n * DD + tid] = __float2bfloat16(fmaxf(val, 0.f));
}

// ------------------------- tail: mean over nodes, fc, sigmoid ---------------
__global__ void reduce_cols_kernel(const __nv_bfloat16* __restrict__ hbuf, float* __restrict__ g) {
    int c = threadIdx.x;
    float a = 0.f;
    for (int r = blockIdx.x; r < NN; r += gridDim.x)
        a += __bfloat162float(hbuf[(size_t)r * DD + c]);
    atomicAdd(&g[c], a);
}

__global__ void fc_kernel(const float* __restrict__ g, const float* __restrict__ Wfc,
                          const float* __restrict__ bfc, float* __restrict__ out) {
    int tid = threadIdx.x;
    float x = g[tid] * (1.0f / (float)NN) * Wfc[tid];
    #pragma unroll
    for (int off = 16; off > 0; off >>= 1)
        x += __shfl_xor_sync(0xffffffffu, x, off);
    __shared__ float ws[4];
    if ((tid & 31) == 0) ws[tid >> 5] = x;
    __syncthreads();
    if (tid == 0) {
        float sum = ws[0] + ws[1] + ws[2] + ws[3] + bfc[0];
        out[0] = 1.f / (1.f + expf(-sum));
    }
}

// ------------------------- launch -------------------------------------------
extern "C" void kernel_launch(void* const* d_in, const int* in_sizes, int n_in,
                              void* d_out, int out_size) {
    (void)in_sizes; (void)n_in; (void)out_size;

    const float* x    = (const float*)d_in[0];
    const int*   eidx = (const int*)d_in[1];
    const int*   src  = eidx;
    const int*   dst  = eidx + EE;
    const float* Wfc  = (const float*)d_in[26];
    const float* bfc  = (const float*)d_in[27];
    float* out = (float*)d_out;

    int *row, *cnt, *cursor, *srcs;
    float *s, *g;
    __nv_bfloat16 *qbp, *hA, *hB, *xb, *wb;
    unsigned char *kfp, *vfp;
    cudaGetSymbolAddress((void**)&row,    g_row);
    cudaGetSymbolAddress((void**)&cnt,    g_cnt);
    cudaGetSymbolAddress((void**)&cursor, g_cursor);
    cudaGetSymbolAddress((void**)&srcs,   g_srcs);
    cudaGetSymbolAddress((void**)&qbp,    g_qb);
    cudaGetSymbolAddress((void**)&kfp,    g_kf);
    cudaGetSymbolAddress((void**)&vfp,    g_vf);
    cudaGetSymbolAddress((void**)&s,      g_s);
    cudaGetSymbolAddress((void**)&hA,     g_hA);
    cudaGetSymbolAddress((void**)&hB,     g_hB);
    cudaGetSymbolAddress((void**)&xb,     g_xb);
    cudaGetSymbolAddress((void**)&wb,     g_wb);
    cudaGetSymbolAddress((void**)&g,      g_g);

    cudaFuncSetAttribute(gemm4_kernel,
                         cudaFuncAttributeMaxDynamicSharedMemorySize, GEMM_SMEM);

    // lazy one-time streams/events (no device memory; capture-legal fork/join)
    static cudaStream_t s2 = nullptr, s3 = nullptr;
    static cudaEvent_t evFork = nullptr, evCSR = nullptr, evW = nullptr;
    if (s2 == nullptr) {
        cudaStreamCreateWithFlags(&s2, cudaStreamNonBlocking);
        cudaStreamCreateWithFlags(&s3, cudaStreamNonBlocking);
        cudaEventCreateWithFlags(&evFork, cudaEventDisableTiming);
        cudaEventCreateWithFlags(&evCSR,  cudaEventDisableTiming);
        cudaEventCreateWithFlags(&evW,    cudaEventDisableTiming);
    }

    size_t wboff[3] = {0, (size_t)64 * WC, (size_t)64 * WC + (size_t)128 * WC};

    // ---- fork: CSR on s2 (as in R14), convW on s3 (the single new change) ----
    cudaEventRecord(evFork, 0);
    cudaStreamWaitEvent(s2, evFork, 0);
    cudaStreamWaitEvent(s3, evFork, 0);

    zero_cnt_kernel<<<(NN + 256) / 256, 256, 0, s2>>>(cnt);
    hist_kernel<<<(EE + 255) / 256, 256, 0, s2>>>(dst, cnt);
    scan_kernel<<<1, 1024, 0, s2>>>(cnt, row, cursor);
    fill_kernel<<<(EE + 255) / 256, 256, 0, s2>>>(src, dst, cursor, srcs);
    cudaEventRecord(evCSR, s2);

    {
        int total = 64 * WC + 2 * 128 * WC;
        convW_all_kernel<<<(total + 255) / 256, 256, 0, s3>>>(
            (const float*)d_in[2],  (const float*)d_in[4],
            (const float*)d_in[6],  (const float*)d_in[8],
            (const float*)d_in[10], (const float*)d_in[12],
            (const float*)d_in[14], (const float*)d_in[16],
            (const float*)d_in[18], (const float*)d_in[20],
            (const float*)d_in[22], (const float*)d_in[24],
            wb);
    }
    cudaEventRecord(evW, s3);

    // main: convX concurrent with CSR/convW
    convX_kernel<<<(NN * 64 + 255) / 256, 256>>>(x, xb, g);
    cudaStreamWaitEvent(0, evW, 0);     // gemm0 needs wb

    const __nv_bfloat16* X = xb;
    int fin = 64;
    __nv_bfloat16* hout = hA;
    for (int l = 0; l < 3; ++l) {
        const float* bq = (const float*)d_in[2 + 8 * l + 1];
        const float* bk = (const float*)d_in[2 + 8 * l + 3];
        const float* bv = (const float*)d_in[2 + 8 * l + 5];
        const float* bs = (const float*)d_in[2 + 8 * l + 7];

        dim3 grid(13, (NN + 127) / 128);
        gemm4_kernel<<<grid, 256, GEMM_SMEM>>>(X, NN, fin, wb + wboff[l],
                                               bq, bk, bv, bs,
                                               qbp, kfp, vfp, s);

        if (l == 0)   // join: CSR results needed from here on
            cudaStreamWaitEvent(0, evCSR, 0);

        attn_kernel<<<NN, 128>>>(qbp, kfp, vfp, s, row, srcs, hout);

        X = hout;
        hout = (hout == hA) ? hB : hA;
        fin = DD;
    }

    // ---- global mean + fc + sigmoid ----
    reduce_cols_kernel<<<256, 128>>>(X, g);
    fc_kernel<<<1, 128>>>(g, Wfc, bfc, out);
}